// round 7
// baseline (speedup 1.0000x reference)
#include <cuda_runtime.h>
#include <cuda_bf16.h>
#include <cstdint>
#include <cstddef>

#define BB 256
#define TT 2048
#define II 64
#define HH 256
#define OO 64
#define FF 16
#define NB2 2   // batches per cluster in the recurrence kernel (occupancy-2 design)

typedef unsigned long long ull;

// ---- packed f32x2 helpers (exact fp32; saves issue slots, not FLOP rate) ---
__device__ __forceinline__ ull pk2(float x, float y) {
    ull r; asm("mov.b64 %0, {%1, %2};" : "=l"(r) : "f"(x), "f"(y)); return r;
}
__device__ __forceinline__ void f2fma(ull& d, ull a, ull b) {
    asm("fma.rn.f32x2 %0, %1, %2, %0;" : "+l"(d) : "l"(a), "l"(b));
}
__device__ __forceinline__ float2 up2(ull v) {
    float2 f; asm("mov.b64 {%0, %1}, %2;" : "=f"(f.x), "=f"(f.y) : "l"(v)); return f;
}

// 512 MB scratch, reused in place: pre0 -> ys0 -> pre1 -> ys1. Layout [t][b][h].
__device__ float g_buf[(size_t)TT * BB * HH];

#define ASTR 68    // As row stride: 16B-aligned, low conflict
#define BSTR 260   // Bs row stride: 16B-aligned pair loads

// ---------------------------------------------------------------------------
// K1: pre0[t,b,n] = x[b,t,:] . W_ih0[n,:] + b_ih0[n] + b_hh0[n]
// ---------------------------------------------------------------------------
__global__ void __launch_bounds__(256)
pre0_kernel(const float* __restrict__ x, const float* __restrict__ Wih,
            const float* __restrict__ bih, const float* __restrict__ bhh) {
    extern __shared__ float sm[];
    float* As = sm;                 // [64 k][ASTR]
    float* Bs = sm + 64 * ASTR;     // [64 k][BSTR]
    const int tid = threadIdx.x;
    const int m0 = blockIdx.x * 64;

    for (int e = tid; e < 64 * 64; e += 256) {
        int r = e >> 6, k = e & 63;
        int m = m0 + r;
        int b = m & (BB - 1);
        int t = m >> 8;
        As[k * ASTR + r] = x[((size_t)b * TT + t) * II + k];
    }
    for (int e = tid; e < 64 * 256; e += 256) {
        int n = e >> 6, k = e & 63;
        Bs[k * BSTR + n] = Wih[n * II + k];
    }
    __syncthreads();

    const int tm = tid & 7;
    const int tn = tid >> 3;
    ull acc2[8][4];
#pragma unroll
    for (int i = 0; i < 8; i++)
#pragma unroll
        for (int j = 0; j < 4; j++) acc2[i][j] = 0ull;

#pragma unroll 8
    for (int k = 0; k < 64; k++) {
        const float4* ar = (const float4*)&As[k * ASTR + tm * 8];
        float4 a0 = ar[0], a1 = ar[1];
        const ulonglong2* br = (const ulonglong2*)&Bs[k * BSTR + tn * 8];
        ulonglong2 q0 = br[0], q1 = br[1];
        ull b2[4] = {q0.x, q0.y, q1.x, q1.y};
        float a[8] = {a0.x, a0.y, a0.z, a0.w, a1.x, a1.y, a1.z, a1.w};
#pragma unroll
        for (int i = 0; i < 8; i++) {
            ull ad = pk2(a[i], a[i]);
#pragma unroll
            for (int j = 0; j < 4; j++) f2fma(acc2[i][j], ad, b2[j]);
        }
    }

#pragma unroll
    for (int j = 0; j < 4; j++) {
        int n0 = tn * 8 + 2 * j;
        float bias0 = bih[n0] + bhh[n0];
        float bias1 = bih[n0 + 1] + bhh[n0 + 1];
#pragma unroll
        for (int i = 0; i < 8; i++) {
            float2 v = up2(acc2[i][j]);
            size_t row = (size_t)(m0 + tm * 8 + i) * HH;
            g_buf[row + n0]     = v.x + bias0;
            g_buf[row + n0 + 1] = v.y + bias1;
        }
    }
}

// ---------------------------------------------------------------------------
// K3: in-place pre1: buf[m,n] = buf[m,:] . W_ih1[n,:] + b_ih1[n] + b_hh1[n]
// ---------------------------------------------------------------------------
__global__ void __launch_bounds__(256)
pre1_kernel(const float* __restrict__ Wih, const float* __restrict__ bih,
            const float* __restrict__ bhh) {
    extern __shared__ float sm[];
    float* As = sm;                    // [256 k][ASTR]
    float* Bs = sm + 256 * ASTR;       // [64 k][BSTR]
    const int tid = threadIdx.x;
    const int m0 = blockIdx.x * 64;

    for (int e = tid; e < 64 * 256; e += 256) {
        int r = e >> 8, k = e & 255;
        As[k * ASTR + r] = g_buf[(size_t)(m0 + r) * HH + k];
    }

    const int tm = tid & 7;
    const int tn = tid >> 3;
    ull acc2[8][4];
#pragma unroll
    for (int i = 0; i < 8; i++)
#pragma unroll
        for (int j = 0; j < 4; j++) acc2[i][j] = 0ull;

    for (int kc = 0; kc < 4; kc++) {
        const int k0 = kc * 64;
        __syncthreads();
        for (int e = tid; e < 64 * 256; e += 256) {
            int n = e >> 6, kk = e & 63;
            Bs[kk * BSTR + n] = Wih[n * HH + k0 + kk];
        }
        __syncthreads();
#pragma unroll 8
        for (int kk = 0; kk < 64; kk++) {
            const float4* ar = (const float4*)&As[(k0 + kk) * ASTR + tm * 8];
            float4 a0 = ar[0], a1 = ar[1];
            const ulonglong2* br = (const ulonglong2*)&Bs[kk * BSTR + tn * 8];
            ulonglong2 q0 = br[0], q1 = br[1];
            ull b2[4] = {q0.x, q0.y, q1.x, q1.y};
            float a[8] = {a0.x, a0.y, a0.z, a0.w, a1.x, a1.y, a1.z, a1.w};
#pragma unroll
            for (int i = 0; i < 8; i++) {
                ull ad = pk2(a[i], a[i]);
#pragma unroll
                for (int j = 0; j < 4; j++) f2fma(acc2[i][j], ad, b2[j]);
            }
        }
    }

#pragma unroll
    for (int j = 0; j < 4; j++) {
        int n0 = tn * 8 + 2 * j;
        float bias0 = bih[n0] + bhh[n0];
        float bias1 = bih[n0 + 1] + bhh[n0 + 1];
#pragma unroll
        for (int i = 0; i < 8; i++) {
            float2 v = up2(acc2[i][j]);
            size_t row = (size_t)(m0 + tm * 8 + i) * HH;
            g_buf[row + n0]     = v.x + bias0;
            g_buf[row + n0 + 1] = v.y + bias1;
        }
    }
}

// ---------------------------------------------------------------------------
// K2: recurrence, occupancy-2 redesign.
// Cluster of 2 CTAs, NB2=2 batches/cluster, grid = 256 CTAs = 128 clusters
// (one wave, 2 CTAs per SM on most SMs). CTA rank c owns k-slice
// [c*128, c*128+128). Thread t computes row n=t over the local slice:
// k-pairs 0..31 from 64 registers, k-pairs 32..63 from a 64 KB smem tile
// (keeps regs <=128 so two CTAs co-reside; while one CTA waits at the
// cluster barrier the other issues FMAs, hiding the exchange latency).
// Cross-slice partials exchanged via DSMEM (double-buffered), one cluster
// barrier per step — same proven protocol as before.
// ---------------------------------------------------------------------------
__global__ void __cluster_dims__(2, 1, 1) __launch_bounds__(256, 2)
rec_kernel(const float* __restrict__ Whh, const float* __restrict__ h0,
           float* __restrict__ hT) {
    extern __shared__ float smd[];
    // layout: Wsm float2[32][256] (16384 f) | h_sm [NB2][128] | ex [2][NB2][128]
    float2* Wsm = (float2*)smd;
    float*  h_sm = smd + 32 * 256 * 2;
    float*  exb  = h_sm + NB2 * 128;

    const int tid = threadIdx.x;
    const int rank = blockIdx.x & 1;
    const int b0 = (blockIdx.x >> 1) * NB2;
    const int kbase = rank * 128;
    const int n = tid;
    const bool own = ((n >> 7) == rank);
    const int nl = n & 127;

    // Register half of W: pairs (2q, 2q+1) for local k 0..63.
    ull W2[32];
    {
        const ulonglong2* wp = (const ulonglong2*)(Whh + (size_t)n * HH + kbase);
#pragma unroll
        for (int q = 0; q < 16; q++) {
            ulonglong2 v = wp[q];
            W2[2 * q]     = v.x;
            W2[2 * q + 1] = v.y;
        }
    }

    // Smem half of W: Wsm[j][nn] = (W[nn][kbase+64+2j], W[nn][kbase+64+2j+1]).
    // n-major inner loop -> coalesced global reads.
    for (int e = tid; e < 32 * 256; e += 256) {
        int nn = e >> 5, j = e & 31;
        Wsm[j * 256 + nn] =
            *(const float2*)(Whh + (size_t)nn * HH + kbase + 64 + 2 * j);
    }

    for (int idx = tid; idx < NB2 * 128; idx += 256) {
        int b = idx >> 7, j = idx & 127;
        h_sm[b * 128 + j] = h0[(b0 + b) * HH + kbase + j];
    }

    uint32_t ex_local = (uint32_t)__cvta_generic_to_shared(exb);
    uint32_t ex_peer;
    asm("mapa.shared::cluster.u32 %0, %1, %2;"
        : "=r"(ex_peer) : "r"(ex_local), "r"(rank ^ 1));

    __syncthreads();  // Wsm / h_sm ready locally
    asm volatile("barrier.cluster.arrive.aligned;\n" ::: "memory");
    asm volatile("barrier.cluster.wait.aligned;\n" ::: "memory");

    for (int t = 0; t < TT; t++) {
        // prefetch pre-activation early (LDG latency overlaps the FMA block)
        float pr[NB2];
        if (own) {
#pragma unroll
            for (int b = 0; b < NB2; b++)
                pr[b] = g_buf[((size_t)t * BB + b0 + b) * HH + n];
        }

        ull acc2[NB2];
#pragma unroll
        for (int b = 0; b < NB2; b++) acc2[b] = 0ull;

        // Register half: local k 0..63 (16 x ulonglong2 of h = 4 k each)
#pragma unroll
        for (int kq = 0; kq < 16; kq++) {
#pragma unroll
            for (int b = 0; b < NB2; b++) {
                ulonglong2 hv = *(const ulonglong2*)&h_sm[b * 128 + kq * 4];
                f2fma(acc2[b], hv.x, W2[2 * kq]);
                f2fma(acc2[b], hv.y, W2[2 * kq + 1]);
            }
        }
        // Smem half: local k 64..127; pairs p=32+j, j = 0..31 in steps of 2
#pragma unroll
        for (int j = 0; j < 32; j += 2) {
            ull w0 = *(const ull*)&Wsm[j * 256 + n];
            ull w1 = *(const ull*)&Wsm[(j + 1) * 256 + n];
#pragma unroll
            for (int b = 0; b < NB2; b++) {
                ulonglong2 hv = *(const ulonglong2*)&h_sm[b * 128 + 64 + 2 * j];
                f2fma(acc2[b], hv.x, w0);
                f2fma(acc2[b], hv.y, w1);
            }
        }

        float s[NB2];
#pragma unroll
        for (int b = 0; b < NB2; b++) {
            float2 v = up2(acc2[b]);
            s[b] = v.x + v.y;
        }

        const int p = t & 1;
        if (!own) {
            uint32_t a = ex_peer + (uint32_t)(((p * NB2) * 128 + nl) * 4);
#pragma unroll
            for (int b = 0; b < NB2; b++)
                asm volatile("st.shared::cluster.f32 [%0], %1;"
                             :: "r"(a + (uint32_t)(b * 128 * 4)), "f"(s[b])
                             : "memory");
        }
        // arrive releases the DSMEM stores; wait acquires the peer's.
        asm volatile("barrier.cluster.arrive.aligned;\n" ::: "memory");
        asm volatile("barrier.cluster.wait.aligned;\n" ::: "memory");

        if (own) {
#pragma unroll
            for (int b = 0; b < NB2; b++) {
                float v = tanhf(pr[b] + s[b] + exb[(p * NB2 + b) * 128 + nl]);
                h_sm[b * 128 + nl] = v;
                g_buf[((size_t)t * BB + b0 + b) * HH + n] = v;
            }
        }
        __syncthreads();  // h_sm writes visible CTA-wide before next step
    }

    if (own) {
#pragma unroll
        for (int b = 0; b < NB2; b++)
            hT[(b0 + b) * HH + n] = h_sm[b * 128 + nl];
    }
}

// ---------------------------------------------------------------------------
// K4: fc over the last F timesteps:
// out[b,f,o] = ys1[T-F+f, b, :] . fc_W[o,:] + fc_b[o]
// ---------------------------------------------------------------------------
__global__ void __launch_bounds__(256)
fc_kernel(const float* __restrict__ Wfc, const float* __restrict__ bfc,
          float* __restrict__ out) {
    __shared__ __align__(16) float xs[FF][HH];
    const int b = blockIdx.x;
    const int tid = threadIdx.x;
    for (int idx = tid; idx < FF * HH; idx += 256) {
        int f = idx >> 8, h = idx & 255;
        int t = TT - FF + f;
        xs[f][h] = g_buf[((size_t)t * BB + b) * HH + h];
    }
    __syncthreads();
    for (int fo = tid; fo < FF * OO; fo += 256) {
        int f = fo >> 6, o = fo & 63;
        float s = 0.f;
        const float4* wr = (const float4*)(Wfc + (size_t)o * HH);
        const float4* xr = (const float4*)&xs[f][0];
#pragma unroll
        for (int q = 0; q < 64; q++) {
            float4 w = wr[q], xv = xr[q];
            s += w.x * xv.x + w.y * xv.y + w.z * xv.z + w.w * xv.w;
        }
        out[((size_t)b * FF + f) * OO + o] = s + bfc[o];
    }
}

// ---------------------------------------------------------------------------
extern "C" void kernel_launch(void* const* d_in, const int* in_sizes, int n_in,
                              void* d_out, int out_size) {
    const float* x      = (const float*)d_in[0];
    const float* hidden = (const float*)d_in[1];
    const float* W_ih0  = (const float*)d_in[2];
    const float* W_hh0  = (const float*)d_in[3];
    const float* b_ih0  = (const float*)d_in[4];
    const float* b_hh0  = (const float*)d_in[5];
    const float* W_ih1  = (const float*)d_in[6];
    const float* W_hh1  = (const float*)d_in[7];
    const float* b_ih1  = (const float*)d_in[8];
    const float* b_hh1  = (const float*)d_in[9];
    const float* fc_W   = (const float*)d_in[10];
    const float* fc_b   = (const float*)d_in[11];

    float* out = (float*)d_out;                 // [B, F, O]
    float* hT  = out + (size_t)BB * FF * OO;    // [2, B, H]

    const int sm1 = (64 * ASTR + 64 * BSTR) * 4;
    const int sm3 = (256 * ASTR + 64 * BSTR) * 4;
    const int smr = (32 * 256 * 2 + NB2 * 128 + 2 * NB2 * 128) * 4;  // ~68.6 KB
    cudaFuncSetAttribute(pre0_kernel, cudaFuncAttributeMaxDynamicSharedMemorySize, sm1);
    cudaFuncSetAttribute(pre1_kernel, cudaFuncAttributeMaxDynamicSharedMemorySize, sm3);
    cudaFuncSetAttribute(rec_kernel,  cudaFuncAttributeMaxDynamicSharedMemorySize, smr);

    const int mblocks = TT * BB / 64;  // 8192
    const int rblocks = 2 * (BB / NB2);  // 256 CTAs = 128 clusters

    pre0_kernel<<<mblocks, 256, sm1>>>(x, W_ih0, b_ih0, b_hh0);
    rec_kernel<<<rblocks, 256, smr>>>(W_hh0, hidden, hT);
    pre1_kernel<<<mblocks, 256, sm3>>>(W_ih1, b_ih1, b_hh1);
    rec_kernel<<<rblocks, 256, smr>>>(W_hh1, hidden + (size_t)BB * HH,
                                      hT + (size_t)BB * HH);
    fc_kernel<<<BB, 256>>>(fc_W, fc_b, out);
}

// round 10
// speedup vs baseline: 1.0542x; 1.0542x over previous
#include <cuda_runtime.h>
#include <cuda_bf16.h>
#include <cstdint>
#include <cstddef>

#define BB 256
#define TT 2048
#define II 64
#define HH 256
#define OO 64
#define FF 16
#define NB 2   // batches per CTA in the recurrence kernel (128 CTAs cover B=256)

typedef unsigned long long ull;

// ---- packed f32x2 helpers (exact fp32; halves issue slots) -----------------
__device__ __forceinline__ ull pk2(float x, float y) {
    ull r; asm("mov.b64 %0, {%1, %2};" : "=l"(r) : "f"(x), "f"(y)); return r;
}
__device__ __forceinline__ void f2fma(ull& d, ull a, ull b) {
    asm("fma.rn.f32x2 %0, %1, %2, %0;" : "+l"(d) : "l"(a), "l"(b));
}
__device__ __forceinline__ float2 up2(ull v) {
    float2 f; asm("mov.b64 {%0, %1}, %2;" : "=f"(f.x), "=f"(f.y) : "l"(v)); return f;
}

// 512 MB scratch, reused in place: pre0 -> ys0 -> pre1 -> ys1. Layout [t][b][h].
__device__ float g_buf[(size_t)TT * BB * HH];

#define ASTR 68    // As row stride: 16B-aligned, low conflict
#define BSTR 260   // Bs row stride: 16B-aligned pair loads

// ---------------------------------------------------------------------------
// K1: pre0[t,b,n] = x[b,t,:] . W_ih0[n,:] + b_ih0[n] + b_hh0[n]
// ---------------------------------------------------------------------------
__global__ void __launch_bounds__(256)
pre0_kernel(const float* __restrict__ x, const float* __restrict__ Wih,
            const float* __restrict__ bih, const float* __restrict__ bhh) {
    extern __shared__ float sm[];
    float* As = sm;                 // [64 k][ASTR]
    float* Bs = sm + 64 * ASTR;     // [64 k][BSTR]
    const int tid = threadIdx.x;
    const int m0 = blockIdx.x * 64;

    for (int e = tid; e < 64 * 64; e += 256) {
        int r = e >> 6, k = e & 63;
        int m = m0 + r;
        int b = m & (BB - 1);
        int t = m >> 8;
        As[k * ASTR + r] = x[((size_t)b * TT + t) * II + k];
    }
    for (int e = tid; e < 64 * 256; e += 256) {
        int n = e >> 6, k = e & 63;
        Bs[k * BSTR + n] = Wih[n * II + k];
    }
    __syncthreads();

    const int tm = tid & 7;
    const int tn = tid >> 3;
    ull acc2[8][4];
#pragma unroll
    for (int i = 0; i < 8; i++)
#pragma unroll
        for (int j = 0; j < 4; j++) acc2[i][j] = 0ull;

#pragma unroll 8
    for (int k = 0; k < 64; k++) {
        const float4* ar = (const float4*)&As[k * ASTR + tm * 8];
        float4 a0 = ar[0], a1 = ar[1];
        const ulonglong2* br = (const ulonglong2*)&Bs[k * BSTR + tn * 8];
        ulonglong2 q0 = br[0], q1 = br[1];
        ull b2[4] = {q0.x, q0.y, q1.x, q1.y};
        float a[8] = {a0.x, a0.y, a0.z, a0.w, a1.x, a1.y, a1.z, a1.w};
#pragma unroll
        for (int i = 0; i < 8; i++) {
            ull ad = pk2(a[i], a[i]);
#pragma unroll
            for (int j = 0; j < 4; j++) f2fma(acc2[i][j], ad, b2[j]);
        }
    }

#pragma unroll
    for (int j = 0; j < 4; j++) {
        int n0 = tn * 8 + 2 * j;
        float bias0 = bih[n0] + bhh[n0];
        float bias1 = bih[n0 + 1] + bhh[n0 + 1];
#pragma unroll
        for (int i = 0; i < 8; i++) {
            float2 v = up2(acc2[i][j]);
            size_t row = (size_t)(m0 + tm * 8 + i) * HH;
            g_buf[row + n0]     = v.x + bias0;
            g_buf[row + n0 + 1] = v.y + bias1;
        }
    }
}

// ---------------------------------------------------------------------------
// K3: in-place pre1: buf[m,n] = buf[m,:] . W_ih1[n,:] + b_ih1[n] + b_hh1[n]
// 32-k B chunks shrink smem to ~101 KB so two blocks co-reside (staging of one
// block's tiles overlaps the other block's FMA phase).
// ---------------------------------------------------------------------------
__global__ void __launch_bounds__(256, 2)
pre1_kernel(const float* __restrict__ Wih, const float* __restrict__ bih,
            const float* __restrict__ bhh) {
    extern __shared__ float sm[];
    float* As = sm;                    // [256 k][ASTR]
    float* Bs = sm + 256 * ASTR;       // [32 k][BSTR]
    const int tid = threadIdx.x;
    const int m0 = blockIdx.x * 64;

    for (int e = tid; e < 64 * 256; e += 256) {
        int r = e >> 8, k = e & 255;
        As[k * ASTR + r] = g_buf[(size_t)(m0 + r) * HH + k];
    }

    const int tm = tid & 7;
    const int tn = tid >> 3;
    ull acc2[8][4];
#pragma unroll
    for (int i = 0; i < 8; i++)
#pragma unroll
        for (int j = 0; j < 4; j++) acc2[i][j] = 0ull;

    for (int kc = 0; kc < 8; kc++) {
        const int k0 = kc * 32;
        __syncthreads();
        for (int e = tid; e < 32 * 256; e += 256) {
            int n = e >> 5, kk = e & 31;
            Bs[kk * BSTR + n] = Wih[n * HH + k0 + kk];
        }
        __syncthreads();
#pragma unroll 8
        for (int kk = 0; kk < 32; kk++) {
            const float4* ar = (const float4*)&As[(k0 + kk) * ASTR + tm * 8];
            float4 a0 = ar[0], a1 = ar[1];
            const ulonglong2* br = (const ulonglong2*)&Bs[kk * BSTR + tn * 8];
            ulonglong2 q0 = br[0], q1 = br[1];
            ull b2[4] = {q0.x, q0.y, q1.x, q1.y};
            float a[8] = {a0.x, a0.y, a0.z, a0.w, a1.x, a1.y, a1.z, a1.w};
#pragma unroll
            for (int i = 0; i < 8; i++) {
                ull ad = pk2(a[i], a[i]);
#pragma unroll
                for (int j = 0; j < 4; j++) f2fma(acc2[i][j], ad, b2[j]);
            }
        }
    }

#pragma unroll
    for (int j = 0; j < 4; j++) {
        int n0 = tn * 8 + 2 * j;
        float bias0 = bih[n0] + bhh[n0];
        float bias1 = bih[n0 + 1] + bhh[n0 + 1];
#pragma unroll
        for (int i = 0; i < 8; i++) {
            float2 v = up2(acc2[i][j]);
            size_t row = (size_t)(m0 + tm * 8 + i) * HH;
            g_buf[row + n0]     = v.x + bias0;
            g_buf[row + n0 + 1] = v.y + bias1;
        }
    }
}

// ---------------------------------------------------------------------------
// K2: recurrence v3 — self-contained CTAs, NO cluster, NO exchange.
// 128 CTAs, NB=2 batches each. Thread n computes the FULL 256-k dot product
// for output row n: W[n][0:128] in 64 ull register pairs, W[n][128:256] read
// from a 128 KB smem tile (reused across batches). h state ping-pongs between
// two smem buffers, so exactly ONE __syncthreads per timestep — the ~490-cyc
// per-step cluster barrier and DSMEM exchange of earlier rounds are gone.
// ---------------------------------------------------------------------------
__global__ void __launch_bounds__(256, 1)
rec_kernel(const float* __restrict__ Whh, const float* __restrict__ h0,
           float* __restrict__ hT) {
    extern __shared__ float smd[];
    // layout: Wsm float2[64 j][256 n] (128 KB) | h ping-pong [2][NB][256]
    float2* Wsm = (float2*)smd;
    float*  hbuf = smd + 64 * 256 * 2;

    const int tid = threadIdx.x;
    const int b0 = blockIdx.x * NB;
    const int n = tid;

    // Register half of W: k 0..127 as pairs (2q, 2q+1).
    ull W2[64];
    {
        const ulonglong2* wp = (const ulonglong2*)(Whh + (size_t)n * HH);
#pragma unroll
        for (int q = 0; q < 32; q++) {
            ulonglong2 v = wp[q];
            W2[2 * q]     = v.x;
            W2[2 * q + 1] = v.y;
        }
    }

    // Smem half: Wsm[j][nn] = (W[nn][128+2j], W[nn][128+2j+1]); coalesced loads.
    for (int e = tid; e < 64 * 256; e += 256) {
        int nn = e >> 6, j = e & 63;
        Wsm[j * 256 + nn] =
            *(const float2*)(Whh + (size_t)nn * HH + 128 + 2 * j);
    }

    for (int idx = tid; idx < NB * HH; idx += 256) {
        int b = idx >> 8, k = idx & 255;
        hbuf[b * 256 + k] = h0[(b0 + b) * HH + k];   // into buffer 0
    }
    __syncthreads();

    for (int t = 0; t < TT; t++) {
        const int p = t & 1;
        const float* cur = hbuf + p * NB * 256;
        float* nxt = hbuf + (p ^ 1) * NB * 256;

        // prefetch pre-activation (LDG latency hides under the FMA block)
        float pr[NB];
#pragma unroll
        for (int b = 0; b < NB; b++)
            pr[b] = g_buf[((size_t)t * BB + b0 + b) * HH + n];

        ull acc2[NB];
#pragma unroll
        for (int b = 0; b < NB; b++) acc2[b] = 0ull;

        // k 0..127 from registers (h loads are warp-broadcast LDS.128)
#pragma unroll
        for (int kq = 0; kq < 32; kq++) {
#pragma unroll
            for (int b = 0; b < NB; b++) {
                ulonglong2 hv = *(const ulonglong2*)&cur[b * 256 + kq * 4];
                f2fma(acc2[b], hv.x, W2[2 * kq]);
                f2fma(acc2[b], hv.y, W2[2 * kq + 1]);
            }
        }
        // k 128..255 from smem (per-lane LDS.64, conflict-free)
#pragma unroll
        for (int j = 0; j < 64; j += 2) {
            ull w0 = *(const ull*)&Wsm[j * 256 + n];
            ull w1 = *(const ull*)&Wsm[(j + 1) * 256 + n];
#pragma unroll
            for (int b = 0; b < NB; b++) {
                ulonglong2 hv = *(const ulonglong2*)&cur[b * 256 + 128 + 2 * j];
                f2fma(acc2[b], hv.x, w0);
                f2fma(acc2[b], hv.y, w1);
            }
        }

#pragma unroll
        for (int b = 0; b < NB; b++) {
            float2 v = up2(acc2[b]);
            float hv = tanhf(pr[b] + v.x + v.y);
            nxt[b * 256 + n] = hv;
            g_buf[((size_t)t * BB + b0 + b) * HH + n] = hv;
        }
        __syncthreads();  // nxt visible to all before it becomes cur
    }

    // TT is even -> final state sits in buffer 0.
#pragma unroll
    for (int b = 0; b < NB; b++)
        hT[(b0 + b) * HH + n] = hbuf[b * 256 + n];
}

// ---------------------------------------------------------------------------
// K4: fc over the last F timesteps:
// out[b,f,o] = ys1[T-F+f, b, :] . fc_W[o,:] + fc_b[o]
// ---------------------------------------------------------------------------
__global__ void __launch_bounds__(256)
fc_kernel(const float* __restrict__ Wfc, const float* __restrict__ bfc,
          float* __restrict__ out) {
    __shared__ __align__(16) float xs[FF][HH];
    const int b = blockIdx.x;
    const int tid = threadIdx.x;
    for (int idx = tid; idx < FF * HH; idx += 256) {
        int f = idx >> 8, h = idx & 255;
        int t = TT - FF + f;
        xs[f][h] = g_buf[((size_t)t * BB + b) * HH + h];
    }
    __syncthreads();
    for (int fo = tid; fo < FF * OO; fo += 256) {
        int f = fo >> 6, o = fo & 63;
        float s = 0.f;
        const float4* wr = (const float4*)(Wfc + (size_t)o * HH);
        const float4* xr = (const float4*)&xs[f][0];
#pragma unroll
        for (int q = 0; q < 64; q++) {
            float4 w = wr[q], xv = xr[q];
            s += w.x * xv.x + w.y * xv.y + w.z * xv.z + w.w * xv.w;
        }
        out[((size_t)b * FF + f) * OO + o] = s + bfc[o];
    }
}

// ---------------------------------------------------------------------------
extern "C" void kernel_launch(void* const* d_in, const int* in_sizes, int n_in,
                              void* d_out, int out_size) {
    const float* x      = (const float*)d_in[0];
    const float* hidden = (const float*)d_in[1];
    const float* W_ih0  = (const float*)d_in[2];
    const float* W_hh0  = (const float*)d_in[3];
    const float* b_ih0  = (const float*)d_in[4];
    const float* b_hh0  = (const float*)d_in[5];
    const float* W_ih1  = (const float*)d_in[6];
    const float* W_hh1  = (const float*)d_in[7];
    const float* b_ih1  = (const float*)d_in[8];
    const float* b_hh1  = (const float*)d_in[9];
    const float* fc_W   = (const float*)d_in[10];
    const float* fc_b   = (const float*)d_in[11];

    float* out = (float*)d_out;                 // [B, F, O]
    float* hT  = out + (size_t)BB * FF * OO;    // [2, B, H]

    const int sm1 = (64 * ASTR + 64 * BSTR) * 4;            // ~84 KB
    const int sm3 = (256 * ASTR + 32 * BSTR) * 4;           // ~101 KB (occ 2)
    const int smr = (64 * 256 * 2 + 2 * NB * 256) * 4;      // 128 KB + 4 KB
    cudaFuncSetAttribute(pre0_kernel, cudaFuncAttributeMaxDynamicSharedMemorySize, sm1);
    cudaFuncSetAttribute(pre1_kernel, cudaFuncAttributeMaxDynamicSharedMemorySize, sm3);
    cudaFuncSetAttribute(rec_kernel,  cudaFuncAttributeMaxDynamicSharedMemorySize, smr);

    const int mblocks = TT * BB / 64;   // 8192
    const int rblocks = BB / NB;        // 128 plain CTAs, no cluster

    pre0_kernel<<<mblocks, 256, sm1>>>(x, W_ih0, b_ih0, b_hh0);
    rec_kernel<<<rblocks, 256, smr>>>(W_hh0, hidden, hT);
    pre1_kernel<<<mblocks, 256, sm3>>>(W_ih1, b_ih1, b_hh1);
    rec_kernel<<<rblocks, 256, smr>>>(W_hh1, hidden + (size_t)BB * HH,
                                      hT + (size_t)BB * HH);
    fc_kernel<<<BB, 256>>>(fc_W, fc_b, out);
}

// round 13
// speedup vs baseline: 1.1556x; 1.0962x over previous
#include <cuda_runtime.h>
#include <cuda_bf16.h>
#include <cstdint>
#include <cstddef>

#define BB 256
#define TT 2048
#define II 64
#define HH 256
#define OO 64
#define FF 16
#define NB 2   // batches per CTA in the recurrence kernel (128 CTAs cover B=256)

typedef unsigned long long ull;

// ---- packed f32x2 helpers (exact fp32) -------------------------------------
__device__ __forceinline__ ull pk2(float x, float y) {
    ull r; asm("mov.b64 %0, {%1, %2};" : "=l"(r) : "f"(x), "f"(y)); return r;
}
__device__ __forceinline__ void f2fma(ull& d, ull a, ull b) {
    asm("fma.rn.f32x2 %0, %1, %2, %0;" : "+l"(d) : "l"(a), "l"(b));
}
__device__ __forceinline__ float2 up2(ull v) {
    float2 f; asm("mov.b64 {%0, %1}, %2;" : "=f"(f.x), "=f"(f.y) : "l"(v)); return f;
}

// 512 MB scratch, reused in place: pre0 -> ys0 -> pre1 -> ys1. Layout [t][b][h].
__device__ float g_buf[(size_t)TT * BB * HH];

#define ASTR 68    // As row stride: 16B-aligned, low conflict
#define BSTR 260   // Bs row stride: 16B-aligned pair loads

// ---------------------------------------------------------------------------
// K1: pre0[t,b,n] = x[b,t,:] . W_ih0[n,:] + b_ih0[n] + b_hh0[n]
// ---------------------------------------------------------------------------
__global__ void __launch_bounds__(256)
pre0_kernel(const float* __restrict__ x, const float* __restrict__ Wih,
            const float* __restrict__ bih, const float* __restrict__ bhh) {
    extern __shared__ float sm[];
    float* As = sm;                 // [64 k][ASTR]
    float* Bs = sm + 64 * ASTR;     // [64 k][BSTR]
    const int tid = threadIdx.x;
    const int m0 = blockIdx.x * 64;

    for (int e = tid; e < 64 * 64; e += 256) {
        int r = e >> 6, k = e & 63;
        int m = m0 + r;
        int b = m & (BB - 1);
        int t = m >> 8;
        As[k * ASTR + r] = x[((size_t)b * TT + t) * II + k];
    }
    for (int e = tid; e < 64 * 256; e += 256) {
        int n = e >> 6, k = e & 63;
        Bs[k * BSTR + n] = Wih[n * II + k];
    }
    __syncthreads();

    const int tm = tid & 7;
    const int tn = tid >> 3;
    ull acc2[8][4];
#pragma unroll
    for (int i = 0; i < 8; i++)
#pragma unroll
        for (int j = 0; j < 4; j++) acc2[i][j] = 0ull;

#pragma unroll 8
    for (int k = 0; k < 64; k++) {
        const float4* ar = (const float4*)&As[k * ASTR + tm * 8];
        float4 a0 = ar[0], a1 = ar[1];
        const ulonglong2* br = (const ulonglong2*)&Bs[k * BSTR + tn * 8];
        ulonglong2 q0 = br[0], q1 = br[1];
        ull b2[4] = {q0.x, q0.y, q1.x, q1.y};
        float a[8] = {a0.x, a0.y, a0.z, a0.w, a1.x, a1.y, a1.z, a1.w};
#pragma unroll
        for (int i = 0; i < 8; i++) {
            ull ad = pk2(a[i], a[i]);
#pragma unroll
            for (int j = 0; j < 4; j++) f2fma(acc2[i][j], ad, b2[j]);
        }
    }

#pragma unroll
    for (int j = 0; j < 4; j++) {
        int n0 = tn * 8 + 2 * j;
        float bias0 = bih[n0] + bhh[n0];
        float bias1 = bih[n0 + 1] + bhh[n0 + 1];
#pragma unroll
        for (int i = 0; i < 8; i++) {
            float2 v = up2(acc2[i][j]);
            size_t row = (size_t)(m0 + tm * 8 + i) * HH;
            g_buf[row + n0]     = v.x + bias0;
            g_buf[row + n0 + 1] = v.y + bias1;
        }
    }
}

// ---------------------------------------------------------------------------
// K3: in-place pre1: buf[m,n] = buf[m,:] . W_ih1[n,:] + b_ih1[n] + b_hh1[n]
// ---------------------------------------------------------------------------
__global__ void __launch_bounds__(256, 2)
pre1_kernel(const float* __restrict__ Wih, const float* __restrict__ bih,
            const float* __restrict__ bhh) {
    extern __shared__ float sm[];
    float* As = sm;                    // [256 k][ASTR]
    float* Bs = sm + 256 * ASTR;       // [32 k][BSTR]
    const int tid = threadIdx.x;
    const int m0 = blockIdx.x * 64;

    for (int e = tid; e < 64 * 256; e += 256) {
        int r = e >> 8, k = e & 255;
        As[k * ASTR + r] = g_buf[(size_t)(m0 + r) * HH + k];
    }

    const int tm = tid & 7;
    const int tn = tid >> 3;
    ull acc2[8][4];
#pragma unroll
    for (int i = 0; i < 8; i++)
#pragma unroll
        for (int j = 0; j < 4; j++) acc2[i][j] = 0ull;

    for (int kc = 0; kc < 8; kc++) {
        const int k0 = kc * 32;
        __syncthreads();
        for (int e = tid; e < 32 * 256; e += 256) {
            int n = e >> 5, kk = e & 31;
            Bs[kk * BSTR + n] = Wih[n * HH + k0 + kk];
        }
        __syncthreads();
#pragma unroll 8
        for (int kk = 0; kk < 32; kk++) {
            const float4* ar = (const float4*)&As[(k0 + kk) * ASTR + tm * 8];
            float4 a0 = ar[0], a1 = ar[1];
            const ulonglong2* br = (const ulonglong2*)&Bs[kk * BSTR + tn * 8];
            ulonglong2 q0 = br[0], q1 = br[1];
            ull b2[4] = {q0.x, q0.y, q1.x, q1.y};
            float a[8] = {a0.x, a0.y, a0.z, a0.w, a1.x, a1.y, a1.z, a1.w};
#pragma unroll
            for (int i = 0; i < 8; i++) {
                ull ad = pk2(a[i], a[i]);
#pragma unroll
                for (int j = 0; j < 4; j++) f2fma(acc2[i][j], ad, b2[j]);
            }
        }
    }

#pragma unroll
    for (int j = 0; j < 4; j++) {
        int n0 = tn * 8 + 2 * j;
        float bias0 = bih[n0] + bhh[n0];
        float bias1 = bih[n0 + 1] + bhh[n0 + 1];
#pragma unroll
        for (int i = 0; i < 8; i++) {
            float2 v = up2(acc2[i][j]);
            size_t row = (size_t)(m0 + tm * 8 + i) * HH;
            g_buf[row + n0]     = v.x + bias0;
            g_buf[row + n0 + 1] = v.y + bias1;
        }
    }
}

// ---------------------------------------------------------------------------
// K2: recurrence v4 — 512-thread k-split CTAs, no cluster.
// 128 CTAs, NB=2 batches each. Thread (half = tid>>8, n = tid&255) computes
// the k-range [half*128, half*128+128) of row n's dot product:
//   - k_local 0..63   from 32 ull register pairs (64 regs)
//   - k_local 64..127 from a 128 KB smem tile (per-lane distinct LDS.128)
// High half deposits partials in psum; low half combines + tanh + stores.
// Two __syncthreads per step. 16 warps/SM (4/SMSP) hide LDS latency; regs
// ~110/thread leave ptxas room to batch loads (MLP) unlike the 214-reg v3.
// ---------------------------------------------------------------------------
__global__ void __launch_bounds__(512, 1)
rec_kernel(const float* __restrict__ Whh, const float* __restrict__ h0,
           float* __restrict__ hT) {
    extern __shared__ float smd[];
    // Wsm: ulonglong2[16][512] = 128 KB | hbuf [2][NB][256] | psum [NB][256]
    ulonglong2* Wsm = (ulonglong2*)smd;
    float* hbuf = smd + 16 * 512 * 4;          // 32768 floats into smd
    float* psum = hbuf + 2 * NB * 256;

    const int tid = threadIdx.x;
    const int half = tid >> 8;        // warps 0-7: half 0, warps 8-15: half 1
    const int n = tid & 255;
    const int b0 = blockIdx.x * NB;
    const int kb = half * 128;

    // Register W: k_local 0..63 as 32 ull pairs; pair i = floats (2i, 2i+1).
    ull W2[32];
    const ulonglong2* wp = (const ulonglong2*)(Whh + (size_t)n * HH + kb);
#pragma unroll
    for (int q = 0; q < 16; q++) {
        ulonglong2 v = wp[q];
        W2[2 * q]     = v.x;
        W2[2 * q + 1] = v.y;
    }
    // Smem W: k_local 64..127. Wsm[j][tid] = floats (64+4j .. 64+4j+3) of
    // this thread's range -> per-lane distinct, conflict-free LDS.128.
#pragma unroll
    for (int j = 0; j < 16; j++)
        Wsm[j * 512 + tid] = wp[16 + j];

    // h init into buffer 0, layout [b][k]
    {
        int b = tid >> 8, k = tid & 255;   // 512 threads cover NB*256
        hbuf[b * 256 + k] = h0[(b0 + b) * HH + k];
    }
    __syncthreads();

    for (int t = 0; t < TT; t++) {
        const int p = t & 1;
        const float* cur = hbuf + p * NB * 256;
        float* nxt = hbuf + (p ^ 1) * NB * 256;

        // low half prefetches pre-activations (hides LDG under FMA block)
        float pr[NB];
        if (half == 0) {
#pragma unroll
            for (int b = 0; b < NB; b++)
                pr[b] = g_buf[((size_t)t * BB + b0 + b) * HH + n];
        }

        ull acc2[NB];
#pragma unroll
        for (int b = 0; b < NB; b++) acc2[b] = 0ull;

        // register part: k_local 0..63 (h loads broadcast within warp)
#pragma unroll
        for (int q4 = 0; q4 < 16; q4++) {
#pragma unroll
            for (int b = 0; b < NB; b++) {
                ulonglong2 hv = *(const ulonglong2*)&cur[b * 256 + kb + q4 * 4];
                f2fma(acc2[b], hv.x, W2[2 * q4]);
                f2fma(acc2[b], hv.y, W2[2 * q4 + 1]);
            }
        }
        // smem part: k_local 64..127
#pragma unroll
        for (int j = 0; j < 16; j++) {
            ulonglong2 w = Wsm[j * 512 + tid];
#pragma unroll
            for (int b = 0; b < NB; b++) {
                ulonglong2 hv =
                    *(const ulonglong2*)&cur[b * 256 + kb + 64 + j * 4];
                f2fma(acc2[b], hv.x, w.x);
                f2fma(acc2[b], hv.y, w.y);
            }
        }

        float s[NB];
#pragma unroll
        for (int b = 0; b < NB; b++) {
            float2 v = up2(acc2[b]);
            s[b] = v.x + v.y;
        }

        if (half == 1) {
#pragma unroll
            for (int b = 0; b < NB; b++) psum[b * 256 + n] = s[b];
        }
        __syncthreads();   // psum visible to low half

        if (half == 0) {
#pragma unroll
            for (int b = 0; b < NB; b++) {
                float hv = tanhf(pr[b] + s[b] + psum[b * 256 + n]);
                nxt[b * 256 + n] = hv;
                g_buf[((size_t)t * BB + b0 + b) * HH + n] = hv;
            }
        }
        __syncthreads();   // nxt visible to all before it becomes cur
    }

    // TT even -> final state in buffer 0
    if (half == 0) {
#pragma unroll
        for (int b = 0; b < NB; b++)
            hT[(b0 + b) * HH + n] = hbuf[b * 256 + n];
    }
}

// ---------------------------------------------------------------------------
// K4: fc over the last F timesteps:
// out[b,f,o] = ys1[T-F+f, b, :] . fc_W[o,:] + fc_b[o]
// ---------------------------------------------------------------------------
__global__ void __launch_bounds__(256)
fc_kernel(const float* __restrict__ Wfc, const float* __restrict__ bfc,
          float* __restrict__ out) {
    __shared__ __align__(16) float xs[FF][HH];
    const int b = blockIdx.x;
    const int tid = threadIdx.x;
    for (int idx = tid; idx < FF * HH; idx += 256) {
        int f = idx >> 8, h = idx & 255;
        int t = TT - FF + f;
        xs[f][h] = g_buf[((size_t)t * BB + b) * HH + h];
    }
    __syncthreads();
    for (int fo = tid; fo < FF * OO; fo += 256) {
        int f = fo >> 6, o = fo & 63;
        float s = 0.f;
        const float4* wr = (const float4*)(Wfc + (size_t)o * HH);
        const float4* xr = (const float4*)&xs[f][0];
#pragma unroll
        for (int q = 0; q < 64; q++) {
            float4 w = wr[q], xv = xr[q];
            s += w.x * xv.x + w.y * xv.y + w.z * xv.z + w.w * xv.w;
        }
        out[((size_t)b * FF + f) * OO + o] = s + bfc[o];
    }
}

// ---------------------------------------------------------------------------
extern "C" void kernel_launch(void* const* d_in, const int* in_sizes, int n_in,
                              void* d_out, int out_size) {
    const float* x      = (const float*)d_in[0];
    const float* hidden = (const float*)d_in[1];
    const float* W_ih0  = (const float*)d_in[2];
    const float* W_hh0  = (const float*)d_in[3];
    const float* b_ih0  = (const float*)d_in[4];
    const float* b_hh0  = (const float*)d_in[5];
    const float* W_ih1  = (const float*)d_in[6];
    const float* W_hh1  = (const float*)d_in[7];
    const float* b_ih1  = (const float*)d_in[8];
    const float* b_hh1  = (const float*)d_in[9];
    const float* fc_W   = (const float*)d_in[10];
    const float* fc_b   = (const float*)d_in[11];

    float* out = (float*)d_out;                 // [B, F, O]
    float* hT  = out + (size_t)BB * FF * OO;    // [2, B, H]

    const int sm1 = (64 * ASTR + 64 * BSTR) * 4;            // ~84 KB
    const int sm3 = (256 * ASTR + 32 * BSTR) * 4;           // ~101 KB (occ 2)
    const int smr = 16 * 512 * 16 + (2 * NB * 256 + NB * 256) * 4; // 134 KB
    cudaFuncSetAttribute(pre0_kernel, cudaFuncAttributeMaxDynamicSharedMemorySize, sm1);
    cudaFuncSetAttribute(pre1_kernel, cudaFuncAttributeMaxDynamicSharedMemorySize, sm3);
    cudaFuncSetAttribute(rec_kernel,  cudaFuncAttributeMaxDynamicSharedMemorySize, smr);

    const int mblocks = TT * BB / 64;   // 8192
    const int rblocks = BB / NB;        // 128 CTAs, 512 threads each

    pre0_kernel<<<mblocks, 256, sm1>>>(x, W_ih0, b_ih0, b_hh0);
    rec_kernel<<<rblocks, 512, smr>>>(W_hh0, hidden, hT);
    pre1_kernel<<<mblocks, 256, sm3>>>(W_ih1, b_ih1, b_hh1);
    rec_kernel<<<rblocks, 512, smr>>>(W_hh1, hidden + (size_t)BB * HH,
                                      hT + (size_t)BB * HH);
    fc_kernel<<<BB, 256>>>(fc_W, fc_b, out);
}